// round 16
// baseline (speedup 1.0000x reference)
#include <cuda_runtime.h>

#define CG 16
#define HH 64
#define WW 64
#define HW 4096
#define GSTR (CG*HW)
#define NT 256
#define NGROUPS 512
#define TSTR 72
#define T2ROWS 36
#define TILE2F (T2ROWS*TSTR)     /* 2592 floats */
#define SCST 2560                /* scratch stride per group (floats) */

__device__ float g_sc[NGROUPS][SCST];

__device__ __forceinline__ float sigf(float x){ return 1.0f/(1.0f+__expf(-x)); }

// ============================ KERNEL 1: stats ============================
__global__ __launch_bounds__(NT, 6) void ema_k1(
    const float* __restrict__ x,
    const float* __restrict__ w1, const float* __restrict__ b1,
    const float* __restrict__ w3, const float* __restrict__ b3,
    const float* __restrict__ w5, const float* __restrict__ b5,
    const float* __restrict__ gnw, const float* __restrict__ gnb,
    const float* __restrict__ ecw, const float* __restrict__ ecb)
{
  __shared__ float s_xh[CG*HH];
  __shared__ float s_xw[CG*WW];
  __shared__ float s_sh[CG*HH];
  __shared__ float s_sw[CG*WW];
  __shared__ float s_w1[CG*CG];
  __shared__ float s_sum[CG], s_sum2[CG];
  __shared__ float s_rect[CG][25];
  __shared__ float s_m1[CG], s_m2[CG], s_m3[CG];
  __shared__ float s_s[3][CG], s_e[3][CG];
  __shared__ float s_a2[CG], s_a3[CG];
  __shared__ float s_mu[CG], s_inv[CG];
  __shared__ float s_k1[CG], s_ca[CG], s_c1p[CG];
  __shared__ float s_Wc[CG][25];
  __shared__ float s_cst;

  const int g = blockIdx.x;
  const int tid = threadIdx.x;
  const int lane = tid & 31;
  const float* gx = x + (size_t)g * GSTR;
  const float4* gx4 = reinterpret_cast<const float4*>(gx);

  if (tid < CG) { s_sum[tid] = 0.f; s_sum2[tid] = 0.f; }
  for (int i = tid; i < CG*WW; i += NT) s_xw[i] = 0.f;   // col-sum accumulators
  if (tid < CG*CG) s_w1[tid] = w1[tid];
  __syncthreads();

  // A: single pass -> row means (shfl) + col sums (per-thread partials + atomics)
  {
    float c0 = 0.f, c1 = 0.f, c2 = 0.f, c3 = 0.f;
    for (int k = 0; k < 64; ++k) {
      int idx = tid + NT*k;
      float4 v = gx4[idx];
      float s = (v.x+v.y)+(v.z+v.w);
      s += __shfl_xor_sync(0xffffffffu, s, 8);
      s += __shfl_xor_sync(0xffffffffu, s, 4);
      s += __shfl_xor_sync(0xffffffffu, s, 2);
      s += __shfl_xor_sync(0xffffffffu, s, 1);
      if ((lane & 15) == 0) s_xh[idx >> 4] = s * (1.0f/WW);
      c0 += v.x; c1 += v.y; c2 += v.z; c3 += v.w;
      if ((k & 3) == 3) {
        float* dst = s_xw + (k >> 2)*WW + (tid & 15)*4;
        atomicAdd(dst+0, c0); atomicAdd(dst+1, c1);
        atomicAdd(dst+2, c2); atomicAdd(dst+3, c3);
        c0 = c1 = c2 = c3 = 0.f;
      }
    }
  }
  __syncthreads();
  for (int i = tid; i < CG*WW; i += NT) s_xw[i] *= (1.0f/HH);
  __syncthreads();

  // B: 1x1 conv + sigmoid gates
  for (int k = 0; k < 8; ++k) {
    int o = tid + NT*k;
    int c = o >> 7, p = o & 127;
    float acc = b1[c];
    const float* src = (p < HH) ? (s_xh + p) : (s_xw + (p - HH));
    #pragma unroll
    for (int ci = 0; ci < CG; ++ci) acc += s_w1[c*CG+ci] * src[ci*64];
    float sgm = sigf(acc);
    if (p < HH) s_sh[c*HH + p] = sgm; else s_sw[c*WW + (p-HH)] = sgm;
  }
  __syncthreads();

  // C: per-channel gated sums
  {
    float ls = 0.f, ls2 = 0.f;
    for (int k = 0; k < 64; ++k) {
      int idx = tid + NT*k;
      int ci = k >> 2;
      int h = (idx >> 4) & 63;
      int w4 = idx & 15;
      float4 v = gx4[idx];
      float shv = s_sh[ci*HH + h];
      const float* swp = s_sw + ci*WW + w4*4;
      float g0 = v.x*shv*swp[0];
      float g1 = v.y*shv*swp[1];
      float g2 = v.z*shv*swp[2];
      float g3 = v.w*shv*swp[3];
      ls  += (g0+g1)+(g2+g3);
      ls2 += (g0*g0+g1*g1)+(g2*g2+g3*g3);
      if ((k & 3) == 3) {
        #pragma unroll
        for (int off = 16; off > 0; off >>= 1) {
          ls  += __shfl_xor_sync(0xffffffffu, ls,  off);
          ls2 += __shfl_xor_sync(0xffffffffu, ls2, off);
        }
        if (lane == 0) { atomicAdd(&s_sum[ci], ls); atomicAdd(&s_sum2[ci], ls2); }
        ls = 0.f; ls2 = 0.f;
      }
    }
  }
  __syncthreads();

  // D1: rectangle sums + stats
  if (tid < CG) {
    int ci = tid;
    float T = 0.f;
    #pragma unroll
    for (int h = 0; h < HH; ++h) T += s_xh[ci*HH + h];
    T *= (float)WW;
    float rs[4] = { s_xh[ci*HH+0]*WW, s_xh[ci*HH+1]*WW, s_xh[ci*HH+62]*WW, s_xh[ci*HH+63]*WW };
    float cs[4] = { s_xw[ci*WW+0]*HH, s_xw[ci*WW+1]*HH, s_xw[ci*WW+62]*HH, s_xw[ci*WW+63]*HH };
    const int RB[4] = {0,1,62,63};
    float corn[4][4];
    for (int a=0;a<4;++a)
      for (int b=0;b<4;++b)
        corn[a][b] = gx[ci*HW + RB[a]*WW + RB[b]];
    const int msk[5] = {0xC, 0x8, 0x0, 0x1, 0x3};
    float rex[5], cex[5];
    for (int j=0;j<5;++j) {
      float r=0.f, c=0.f;
      for (int b=0;b<4;++b) if ((msk[j]>>b)&1) { r += rs[b]; c += cs[b]; }
      rex[j]=r; cex[j]=c;
    }
    for (int jh=0;jh<5;++jh)
      for (int jw=0;jw<5;++jw) {
        float r = T - rex[jh] - cex[jw];
        for (int a=0;a<4;++a) if ((msk[jh]>>a)&1)
          for (int b=0;b<4;++b) if ((msk[jw]>>b)&1)
            r += corn[a][b];
        s_rect[ci][jh*5+jw] = r;
      }
    float mu  = s_sum[ci]  * (1.0f/HW);
    float var = s_sum2[ci] * (1.0f/HW) - mu*mu;
    s_mu[ci]  = mu;
    s_inv[ci] = rsqrtf(var + 1e-5f);
  }
  __syncthreads();

  // D3: channel means — parallel over 256 threads, thread=(c,ci) pair
  {
    int c = tid >> 4, ci = tid & 15;
    const float* w3p = w3 + (c*CG + ci)*9;
    const float* w5p = w5 + (c*CG + ci)*25;
    float a2p = 0.f, a3p = 0.f;
    #pragma unroll
    for (int kh=0;kh<3;++kh)
      #pragma unroll
      for (int kw=0;kw<3;++kw)
        a2p += w3p[kh*3+kw] * s_rect[ci][(kh+1)*5 + (kw+1)];
    #pragma unroll
    for (int kk=0;kk<25;++kk) a3p += w5p[kk] * s_rect[ci][kk];
    #pragma unroll
    for (int off = 8; off > 0; off >>= 1) {
      a2p += __shfl_xor_sync(0xffffffffu, a2p, off);
      a3p += __shfl_xor_sync(0xffffffffu, a3p, off);
    }
    if (ci == 0) {
      s_m1[c] = gnb[c];
      s_m2[c] = a2p * (1.0f/HW) + b3[c];
      s_m3[c] = a3p * (1.0f/HW) + b5[c];
    }
  }
  __syncthreads();

  // D4: softmax + eca
  if (tid < 48) {
    int j = tid >> 4, c = tid & 15;
    const float* m = (j==0) ? s_m1 : ((j==1) ? s_m2 : s_m3);
    float mx = m[0];
    for (int i=1;i<CG;++i) mx = fmaxf(mx, m[i]);
    float sum = 0.f;
    for (int i=0;i<CG;++i) sum += __expf(m[i]-mx);
    s_s[j][c] = __expf(m[c]-mx) / sum;
    float prev = (c>0)     ? m[c-1] : 0.f;
    float nxt  = (c<CG-1)  ? m[c+1] : 0.f;
    s_e[j][c] = sigf(ecw[0]*prev + ecw[1]*m[c] + ecw[2]*nxt + ecb[0]);
  }
  __syncthreads();

  // D5: coefficients
  if (tid < CG) {
    int c = tid;
    s_ca[c] = s_e[0][c] + s_e[1][c] + s_e[2][c];
    float a1 = s_s[1][c] + s_s[2][c];
    float a2 = s_s[0][c] + s_s[2][c];
    float a3 = s_s[0][c] + s_s[1][c];
    s_a2[c] = a2; s_a3[c] = a3;
    float iv = s_inv[c]*gnw[c];
    s_k1[c]  = a1 * iv;
    s_c1p[c] = a1*(gnb[c] - s_mu[c]*iv) + a2*b3[c] + a3*b5[c];
  }
  __syncthreads();
  if (tid == 0) {
    float cst = 0.f;
    for (int c=0;c<CG;++c) cst += s_c1p[c];
    s_cst = cst;
  }
  // D6: effective 5x5 kernel
  for (int o = tid; o < CG*25; o += NT) {
    int ci = o / 25, k = o % 25;
    int dh = k / 5, dw = k % 5;
    float wv = 0.f;
    for (int c=0;c<CG;++c) wv += s_a3[c] * w5[(c*CG+ci)*25 + k];
    if (dh>=1 && dh<=3 && dw>=1 && dw<=3) {
      int k3 = (dh-1)*3 + (dw-1);
      for (int c=0;c<CG;++c) wv += s_a2[c] * w3[(c*CG+ci)*9 + k3];
    }
    s_Wc[ci][k] = wv;
  }
  // D7: fold k1 into h-gate
  for (int o = tid; o < CG*HH; o += NT) {
    int ci = o >> 6;
    s_sh[o] *= s_k1[ci];
  }
  __syncthreads();

  // write scratch
  float* sc = g_sc[g];
  for (int i = tid; i < CG*HH; i += NT) sc[i] = s_sh[i];
  for (int i = tid; i < CG*WW; i += NT) sc[1024 + i] = s_sw[i];
  for (int i = tid; i < CG*25; i += NT) sc[2048 + i] = s_Wc[i/25][i%25];
  if (tid < CG) sc[2448 + tid] = s_ca[tid];
  if (tid == 0) sc[2464] = s_cst;
}

// ===================== KERNEL 2: conv + scale (half-group) =====================
__global__ __launch_bounds__(NT, 4) void ema_k2(
    const float* __restrict__ x, float* __restrict__ out)
{
  __shared__ float s_sh[CG*HH];
  __shared__ float s_sw[CG*WW];
  __shared__ float s_Wc[CG][25];
  __shared__ float s_ca[CG];
  __shared__ float s_cst;
  extern __shared__ float s_tiles[];   // 2*TILE2F floats

  const int bid = blockIdx.x;
  const int g = bid >> 1;
  const int half = bid & 1;
  const int hb = half * 32;            // first output row (global)
  const int tid = threadIdx.x;
  const int lane = tid & 31;
  const int wid = tid >> 5;            // 0..7
  const int rw8 = (wid & 3) * 8;       // local row-group base (0..24)
  const int wl  = (wid >> 2) * 32 + lane;  // col 0..63

  const float* gx = x + (size_t)g * GSTR;
  float* gout = out + (size_t)g * GSTR;
  const float4* gx4 = reinterpret_cast<const float4*>(gx);
  const float* sc = g_sc[g];

  // load stats, zero tiles (halo + OOB rows stay 0)
  for (int i = tid; i < 2*TILE2F; i += NT) s_tiles[i] = 0.f;
  for (int i = tid; i < CG*HH; i += NT) s_sh[i] = sc[i];
  for (int i = tid; i < CG*WW; i += NT) s_sw[i] = sc[1024 + i];
  for (int i = tid; i < CG*25; i += NT) s_Wc[i/25][i%25] = sc[2048 + i];
  if (tid < CG) s_ca[tid] = sc[2448 + tid];
  if (tid == 0) s_cst = sc[2464];

  // tile refill geometry: 34 valid rows = 544 float4s
  const int hsrc0 = half ? 30 : 0;     // global row of f=0
  const int ldst0 = half ? 0 : 2;      // local tile row of f=0
  __syncthreads();

  // preload tile ci=0 into buffer 0
  for (int f = tid; f < 544; f += NT) {
    int hr = f >> 4, c4 = f & 15;
    *reinterpret_cast<float4*>(s_tiles + (ldst0 + hr)*TSTR + 4 + c4*4) =
        gx4[(hsrc0 + hr)*16 + c4];
  }
  __syncthreads();

  float acc[8];
  #pragma unroll
  for (int i=0;i<8;++i) acc[i] = 0.f;

#define CONTRIB(o) { const int _dh = r - (o); \
    acc[o] += wc[_dh*5+0]*v[0]+wc[_dh*5+1]*v[1]+wc[_dh*5+2]*v[2]+wc[_dh*5+3]*v[3]+wc[_dh*5+4]*v[4]; }

#define ROWS(rlo, rhi) \
    _Pragma("unroll") \
    for (int r = rlo; r < rhi; ++r) { \
      const float* trow = cur + (rw8 + r)*TSTR + 2 + wl; \
      float v[5]; \
      _Pragma("unroll") \
      for (int d=0; d<5; ++d) v[d] = trow[d]; \
      if (r < 5)             CONTRIB(0); \
      if (r >= 1 && r < 6)   CONTRIB(1); \
      if (r >= 2 && r < 7)   CONTRIB(2); \
      if (r >= 3 && r < 8)   CONTRIB(3); \
      if (r >= 4 && r < 9)   CONTRIB(4); \
      if (r >= 5 && r < 10)  CONTRIB(5); \
      if (r >= 6 && r < 11)  CONTRIB(6); \
      if (r >= 7)            CONTRIB(7); \
      if (r >= 2 && r < 10) { \
        float kh = s_sh[ci*HH + hb + rw8 + r - 2]; \
        acc[r-2] += kh*sw*v[2]; \
      } \
    }

  for (int ci = 0; ci < CG; ++ci) {
    const float* cur = s_tiles + (ci&1)*TILE2F;
    float* nxt = s_tiles + ((ci+1)&1)*TILE2F;
    const bool more = (ci + 1 < CG);
    const float4* nsrc = gx4 + (ci+1)*(HW/4);

    float wc[25];
    #pragma unroll
    for (int k=0;k<25;++k) wc[k] = s_Wc[ci][k];
    float sw = s_sw[ci*WW + wl];

    float4 p;
    if (more) p = nsrc[(hsrc0 + (tid >> 4))*16 + (tid & 15)];        // chunk0
    ROWS(0, 4)
    if (more) {
      *reinterpret_cast<float4*>(nxt + (ldst0 + (tid>>4))*TSTR + 4 + (tid&15)*4) = p;
      int f = tid + NT;
      p = nsrc[(hsrc0 + (f >> 4))*16 + (f & 15)];                    // chunk1
    }
    ROWS(4, 8)
    if (more) {
      int f = tid + NT;
      *reinterpret_cast<float4*>(nxt + (ldst0 + (f>>4))*TSTR + 4 + (f&15)*4) = p;
      if (tid < 32) {
        int f2 = tid + 2*NT;
        p = nsrc[(hsrc0 + (f2 >> 4))*16 + (f2 & 15)];                // chunk2
      }
    }
    ROWS(8, 12)
    if (more && tid < 32) {
      int f2 = tid + 2*NT;
      *reinterpret_cast<float4*>(nxt + (ldst0 + (f2>>4))*TSTR + 4 + (f2&15)*4) = p;
    }
    __syncthreads();
  }
#undef ROWS
#undef CONTRIB

  // stage weights (buffer 0 free: last E iter read buffer 1)
  float* s_wv = s_tiles;
  {
    float cst = s_cst;
    #pragma unroll
    for (int o=0;o<8;++o) s_wv[(rw8+o)*WW + wl] = sigf(acc[o] + cst);
  }
  __syncthreads();

  // F: vectorized scale of rows [hb, hb+32)
  {
    const float4* wv4 = reinterpret_cast<const float4*>(s_wv);
    float4* gout4 = reinterpret_cast<float4*>(gout);
    for (int ci = 0; ci < CG; ++ci) {
      float cav = s_ca[ci];
      #pragma unroll
      for (int k=0;k<2;++k) {
        int f = tid + NT*k;                    // 0..511
        int gi = ci*(HW/4) + hb*16 + f;
        float4 xv = gx4[gi];
        float4 wv = wv4[f];
        float4 ov;
        ov.x = xv.x * (cav * wv.x);
        ov.y = xv.y * (cav * wv.y);
        ov.z = xv.z * (cav * wv.z);
        ov.w = xv.w * (cav * wv.w);
        gout4[gi] = ov;
      }
    }
  }
}

extern "C" void kernel_launch(void* const* d_in, const int* in_sizes, int n_in,
                              void* d_out, int out_size) {
  (void)in_sizes; (void)n_in; (void)out_size;
  const int dyn2 = 2 * TILE2F * sizeof(float);   // 20736 B
  cudaFuncSetAttribute(ema_k2, cudaFuncAttributeMaxDynamicSharedMemorySize, dyn2);
  ema_k1<<<NGROUPS, NT>>>(
      (const float*)d_in[0],
      (const float*)d_in[1], (const float*)d_in[2],
      (const float*)d_in[3], (const float*)d_in[4],
      (const float*)d_in[5], (const float*)d_in[6],
      (const float*)d_in[7], (const float*)d_in[8],
      (const float*)d_in[9], (const float*)d_in[10]);
  ema_k2<<<2*NGROUPS, NT, dyn2>>>((const float*)d_in[0], (float*)d_out);
}

// round 17
// speedup vs baseline: 1.0564x; 1.0564x over previous
#include <cuda_runtime.h>

#define CG 16
#define HH 64
#define WW 64
#define HW 4096
#define GSTR (CG*HW)
#define NT 256
#define NGROUPS 512
#define TSTR 72
#define T2ROWS 36
#define TILE2F (T2ROWS*TSTR)     /* 2592 floats */
#define SCST 2560                /* scratch stride per group (floats) */

__device__ float g_sc[NGROUPS][SCST];

__device__ __forceinline__ float sigf(float x){ return 1.0f/(1.0f+__expf(-x)); }

// ============================ KERNEL 1: stats ============================
__global__ __launch_bounds__(NT, 4) void ema_k1(
    const float* __restrict__ x,
    const float* __restrict__ w1, const float* __restrict__ b1,
    const float* __restrict__ w3, const float* __restrict__ b3,
    const float* __restrict__ w5, const float* __restrict__ b5,
    const float* __restrict__ gnw, const float* __restrict__ gnb,
    const float* __restrict__ ecw, const float* __restrict__ ecb)
{
  __shared__ float s_xh[CG*HH];
  __shared__ float s_xw[CG*WW];
  __shared__ float s_sh[CG*HH];
  __shared__ float s_sw[CG*WW];
  __shared__ float s_w1[CG*CG];
  __shared__ float s_sum[CG], s_sum2[CG];
  __shared__ float s_rect[CG][25];
  __shared__ float s_m1[CG], s_m2[CG], s_m3[CG];
  __shared__ float s_s[3][CG], s_e[3][CG];
  __shared__ float s_a2[CG], s_a3[CG];
  __shared__ float s_mu[CG], s_inv[CG];
  __shared__ float s_k1[CG], s_ca[CG], s_c1p[CG];
  __shared__ float s_Wc[CG][25];
  __shared__ float s_cst;

  const int g = blockIdx.x;
  const int tid = threadIdx.x;
  const int lane = tid & 31;
  const float* gx = x + (size_t)g * GSTR;
  const float4* gx4 = reinterpret_cast<const float4*>(gx);

  if (tid < CG) { s_sum[tid] = 0.f; s_sum2[tid] = 0.f; }
  for (int i = tid; i < CG*WW; i += NT) s_xw[i] = 0.f;   // col-sum accumulators
  if (tid < CG*CG) s_w1[tid] = w1[tid];
  __syncthreads();

  // A: single pass, UNROLL-4 with hoisted loads (MLP=4).
  // k multiple of 4 -> all 4 j's share channel ci = k>>2; flush at j=3.
  {
    for (int k = 0; k < 64; k += 4) {
      float4 va[4];
      #pragma unroll
      for (int j=0;j<4;++j) va[j] = gx4[tid + NT*(k+j)];
      float c0 = 0.f, c1 = 0.f, c2 = 0.f, c3 = 0.f;
      #pragma unroll
      for (int j=0;j<4;++j) {
        float4 v = va[j];
        float s = (v.x+v.y)+(v.z+v.w);
        s += __shfl_xor_sync(0xffffffffu, s, 8);
        s += __shfl_xor_sync(0xffffffffu, s, 4);
        s += __shfl_xor_sync(0xffffffffu, s, 2);
        s += __shfl_xor_sync(0xffffffffu, s, 1);
        if ((lane & 15) == 0) s_xh[(tid + NT*(k+j)) >> 4] = s * (1.0f/WW);
        c0 += v.x; c1 += v.y; c2 += v.z; c3 += v.w;
      }
      float* dst = s_xw + (k >> 2)*WW + (tid & 15)*4;
      atomicAdd(dst+0, c0); atomicAdd(dst+1, c1);
      atomicAdd(dst+2, c2); atomicAdd(dst+3, c3);
    }
  }
  __syncthreads();
  for (int i = tid; i < CG*WW; i += NT) s_xw[i] *= (1.0f/HH);
  __syncthreads();

  // B: 1x1 conv + sigmoid gates
  for (int k = 0; k < 8; ++k) {
    int o = tid + NT*k;
    int c = o >> 7, p = o & 127;
    float acc = b1[c];
    const float* src = (p < HH) ? (s_xh + p) : (s_xw + (p - HH));
    #pragma unroll
    for (int ci = 0; ci < CG; ++ci) acc += s_w1[c*CG+ci] * src[ci*64];
    float sgm = sigf(acc);
    if (p < HH) s_sh[c*HH + p] = sgm; else s_sw[c*WW + (p-HH)] = sgm;
  }
  __syncthreads();

  // C: per-channel gated sums, UNROLL-4 with hoisted loads (MLP=4)
  {
    for (int k = 0; k < 64; k += 4) {
      float4 va[4];
      #pragma unroll
      for (int j=0;j<4;++j) va[j] = gx4[tid + NT*(k+j)];
      int ci = k >> 2;
      int w4 = tid & 15;
      const float* swp = s_sw + ci*WW + w4*4;
      float sw0 = swp[0], sw1 = swp[1], sw2 = swp[2], sw3 = swp[3];
      float ls = 0.f, ls2 = 0.f;
      #pragma unroll
      for (int j=0;j<4;++j) {
        float4 v = va[j];
        int h = ((tid + NT*(k+j)) >> 4) & 63;
        float shv = s_sh[ci*HH + h];
        float g0 = v.x*shv*sw0;
        float g1 = v.y*shv*sw1;
        float g2 = v.z*shv*sw2;
        float g3 = v.w*shv*sw3;
        ls  += (g0+g1)+(g2+g3);
        ls2 += (g0*g0+g1*g1)+(g2*g2+g3*g3);
      }
      #pragma unroll
      for (int off = 16; off > 0; off >>= 1) {
        ls  += __shfl_xor_sync(0xffffffffu, ls,  off);
        ls2 += __shfl_xor_sync(0xffffffffu, ls2, off);
      }
      if (lane == 0) { atomicAdd(&s_sum[ci], ls); atomicAdd(&s_sum2[ci], ls2); }
    }
  }
  __syncthreads();

  // D1: rectangle sums + stats
  if (tid < CG) {
    int ci = tid;
    float T = 0.f;
    #pragma unroll
    for (int h = 0; h < HH; ++h) T += s_xh[ci*HH + h];
    T *= (float)WW;
    float rs[4] = { s_xh[ci*HH+0]*WW, s_xh[ci*HH+1]*WW, s_xh[ci*HH+62]*WW, s_xh[ci*HH+63]*WW };
    float cs[4] = { s_xw[ci*WW+0]*HH, s_xw[ci*WW+1]*HH, s_xw[ci*WW+62]*HH, s_xw[ci*WW+63]*HH };
    const int RB[4] = {0,1,62,63};
    float corn[4][4];
    for (int a=0;a<4;++a)
      for (int b=0;b<4;++b)
        corn[a][b] = gx[ci*HW + RB[a]*WW + RB[b]];
    const int msk[5] = {0xC, 0x8, 0x0, 0x1, 0x3};
    float rex[5], cex[5];
    for (int j=0;j<5;++j) {
      float r=0.f, c=0.f;
      for (int b=0;b<4;++b) if ((msk[j]>>b)&1) { r += rs[b]; c += cs[b]; }
      rex[j]=r; cex[j]=c;
    }
    for (int jh=0;jh<5;++jh)
      for (int jw=0;jw<5;++jw) {
        float r = T - rex[jh] - cex[jw];
        for (int a=0;a<4;++a) if ((msk[jh]>>a)&1)
          for (int b=0;b<4;++b) if ((msk[jw]>>b)&1)
            r += corn[a][b];
        s_rect[ci][jh*5+jw] = r;
      }
    float mu  = s_sum[ci]  * (1.0f/HW);
    float var = s_sum2[ci] * (1.0f/HW) - mu*mu;
    s_mu[ci]  = mu;
    s_inv[ci] = rsqrtf(var + 1e-5f);
  }
  __syncthreads();

  // D3: channel means — parallel over 256 threads, thread=(c,ci) pair
  {
    int c = tid >> 4, ci = tid & 15;
    const float* w3p = w3 + (c*CG + ci)*9;
    const float* w5p = w5 + (c*CG + ci)*25;
    float a2p = 0.f, a3p = 0.f;
    #pragma unroll
    for (int kh=0;kh<3;++kh)
      #pragma unroll
      for (int kw=0;kw<3;++kw)
        a2p += w3p[kh*3+kw] * s_rect[ci][(kh+1)*5 + (kw+1)];
    #pragma unroll
    for (int kk=0;kk<25;++kk) a3p += w5p[kk] * s_rect[ci][kk];
    #pragma unroll
    for (int off = 8; off > 0; off >>= 1) {
      a2p += __shfl_xor_sync(0xffffffffu, a2p, off);
      a3p += __shfl_xor_sync(0xffffffffu, a3p, off);
    }
    if (ci == 0) {
      s_m1[c] = gnb[c];
      s_m2[c] = a2p * (1.0f/HW) + b3[c];
      s_m3[c] = a3p * (1.0f/HW) + b5[c];
    }
  }
  __syncthreads();

  // D4: softmax + eca
  if (tid < 48) {
    int j = tid >> 4, c = tid & 15;
    const float* m = (j==0) ? s_m1 : ((j==1) ? s_m2 : s_m3);
    float mx = m[0];
    for (int i=1;i<CG;++i) mx = fmaxf(mx, m[i]);
    float sum = 0.f;
    for (int i=0;i<CG;++i) sum += __expf(m[i]-mx);
    s_s[j][c] = __expf(m[c]-mx) / sum;
    float prev = (c>0)     ? m[c-1] : 0.f;
    float nxt  = (c<CG-1)  ? m[c+1] : 0.f;
    s_e[j][c] = sigf(ecw[0]*prev + ecw[1]*m[c] + ecw[2]*nxt + ecb[0]);
  }
  __syncthreads();

  // D5: coefficients
  if (tid < CG) {
    int c = tid;
    s_ca[c] = s_e[0][c] + s_e[1][c] + s_e[2][c];
    float a1 = s_s[1][c] + s_s[2][c];
    float a2 = s_s[0][c] + s_s[2][c];
    float a3 = s_s[0][c] + s_s[1][c];
    s_a2[c] = a2; s_a3[c] = a3;
    float iv = s_inv[c]*gnw[c];
    s_k1[c]  = a1 * iv;
    s_c1p[c] = a1*(gnb[c] - s_mu[c]*iv) + a2*b3[c] + a3*b5[c];
  }
  __syncthreads();
  if (tid == 0) {
    float cst = 0.f;
    for (int c=0;c<CG;++c) cst += s_c1p[c];
    s_cst = cst;
  }
  // D6: effective 5x5 kernel
  for (int o = tid; o < CG*25; o += NT) {
    int ci = o / 25, k = o % 25;
    int dh = k / 5, dw = k % 5;
    float wv = 0.f;
    for (int c=0;c<CG;++c) wv += s_a3[c] * w5[(c*CG+ci)*25 + k];
    if (dh>=1 && dh<=3 && dw>=1 && dw<=3) {
      int k3 = (dh-1)*3 + (dw-1);
      for (int c=0;c<CG;++c) wv += s_a2[c] * w3[(c*CG+ci)*9 + k3];
    }
    s_Wc[ci][k] = wv;
  }
  // D7: fold k1 into h-gate
  for (int o = tid; o < CG*HH; o += NT) {
    int ci = o >> 6;
    s_sh[o] *= s_k1[ci];
  }
  __syncthreads();

  // write scratch
  float* sc = g_sc[g];
  for (int i = tid; i < CG*HH; i += NT) sc[i] = s_sh[i];
  for (int i = tid; i < CG*WW; i += NT) sc[1024 + i] = s_sw[i];
  for (int i = tid; i < CG*25; i += NT) sc[2048 + i] = s_Wc[i/25][i%25];
  if (tid < CG) sc[2448 + tid] = s_ca[tid];
  if (tid == 0) sc[2464] = s_cst;
}

// ===================== KERNEL 2: conv + scale (half-group) =====================
__global__ __launch_bounds__(NT, 4) void ema_k2(
    const float* __restrict__ x, float* __restrict__ out)
{
  __shared__ float s_sh[CG*HH];
  __shared__ float s_sw[CG*WW];
  __shared__ float s_Wc[CG][25];
  __shared__ float s_ca[CG];
  __shared__ float s_cst;
  extern __shared__ float s_tiles[];   // 2*TILE2F floats

  const int bid = blockIdx.x;
  const int g = bid >> 1;
  const int half = bid & 1;
  const int hb = half * 32;            // first output row (global)
  const int tid = threadIdx.x;
  const int lane = tid & 31;
  const int wid = tid >> 5;            // 0..7
  const int rw8 = (wid & 3) * 8;       // local row-group base (0..24)
  const int wl  = (wid >> 2) * 32 + lane;  // col 0..63

  const float* gx = x + (size_t)g * GSTR;
  float* gout = out + (size_t)g * GSTR;
  const float4* gx4 = reinterpret_cast<const float4*>(gx);
  const float* sc = g_sc[g];

  // load stats, zero tiles (halo + OOB rows stay 0)
  for (int i = tid; i < 2*TILE2F; i += NT) s_tiles[i] = 0.f;
  for (int i = tid; i < CG*HH; i += NT) s_sh[i] = sc[i];
  for (int i = tid; i < CG*WW; i += NT) s_sw[i] = sc[1024 + i];
  for (int i = tid; i < CG*25; i += NT) s_Wc[i/25][i%25] = sc[2048 + i];
  if (tid < CG) s_ca[tid] = sc[2448 + tid];
  if (tid == 0) s_cst = sc[2464];

  // tile refill geometry: 34 valid rows = 544 float4s
  const int hsrc0 = half ? 30 : 0;     // global row of f=0
  const int ldst0 = half ? 0 : 2;      // local tile row of f=0
  __syncthreads();

  // preload tile ci=0 into buffer 0
  for (int f = tid; f < 544; f += NT) {
    int hr = f >> 4, c4 = f & 15;
    *reinterpret_cast<float4*>(s_tiles + (ldst0 + hr)*TSTR + 4 + c4*4) =
        gx4[(hsrc0 + hr)*16 + c4];
  }
  __syncthreads();

  float acc[8];
  #pragma unroll
  for (int i=0;i<8;++i) acc[i] = 0.f;

#define CONTRIB(o) { const int _dh = r - (o); \
    acc[o] += wc[_dh*5+0]*v[0]+wc[_dh*5+1]*v[1]+wc[_dh*5+2]*v[2]+wc[_dh*5+3]*v[3]+wc[_dh*5+4]*v[4]; }

#define ROWS(rlo, rhi) \
    _Pragma("unroll") \
    for (int r = rlo; r < rhi; ++r) { \
      const float* trow = cur + (rw8 + r)*TSTR + 2 + wl; \
      float v[5]; \
      _Pragma("unroll") \
      for (int d=0; d<5; ++d) v[d] = trow[d]; \
      if (r < 5)             CONTRIB(0); \
      if (r >= 1 && r < 6)   CONTRIB(1); \
      if (r >= 2 && r < 7)   CONTRIB(2); \
      if (r >= 3 && r < 8)   CONTRIB(3); \
      if (r >= 4 && r < 9)   CONTRIB(4); \
      if (r >= 5 && r < 10)  CONTRIB(5); \
      if (r >= 6 && r < 11)  CONTRIB(6); \
      if (r >= 7)            CONTRIB(7); \
      if (r >= 2 && r < 10) { \
        float kh = s_sh[ci*HH + hb + rw8 + r - 2]; \
        acc[r-2] += kh*sw*v[2]; \
      } \
    }

  for (int ci = 0; ci < CG; ++ci) {
    const float* cur = s_tiles + (ci&1)*TILE2F;
    float* nxt = s_tiles + ((ci+1)&1)*TILE2F;
    const bool more = (ci + 1 < CG);
    const float4* nsrc = gx4 + (ci+1)*(HW/4);

    float wc[25];
    #pragma unroll
    for (int k=0;k<25;++k) wc[k] = s_Wc[ci][k];
    float sw = s_sw[ci*WW + wl];

    float4 p;
    if (more) p = nsrc[(hsrc0 + (tid >> 4))*16 + (tid & 15)];        // chunk0
    ROWS(0, 4)
    if (more) {
      *reinterpret_cast<float4*>(nxt + (ldst0 + (tid>>4))*TSTR + 4 + (tid&15)*4) = p;
      int f = tid + NT;
      p = nsrc[(hsrc0 + (f >> 4))*16 + (f & 15)];                    // chunk1
    }
    ROWS(4, 8)
    if (more) {
      int f = tid + NT;
      *reinterpret_cast<float4*>(nxt + (ldst0 + (f>>4))*TSTR + 4 + (f&15)*4) = p;
      if (tid < 32) {
        int f2 = tid + 2*NT;
        p = nsrc[(hsrc0 + (f2 >> 4))*16 + (f2 & 15)];                // chunk2
      }
    }
    ROWS(8, 12)
    if (more && tid < 32) {
      int f2 = tid + 2*NT;
      *reinterpret_cast<float4*>(nxt + (ldst0 + (f2>>4))*TSTR + 4 + (f2&15)*4) = p;
    }
    __syncthreads();
  }
#undef ROWS
#undef CONTRIB

  // stage weights (buffer 0 free: last E iter read buffer 1)
  float* s_wv = s_tiles;
  {
    float cst = s_cst;
    #pragma unroll
    for (int o=0;o<8;++o) s_wv[(rw8+o)*WW + wl] = sigf(acc[o] + cst);
  }
  __syncthreads();

  // F: vectorized scale of rows [hb, hb+32)
  {
    const float4* wv4 = reinterpret_cast<const float4*>(s_wv);
    float4* gout4 = reinterpret_cast<float4*>(gout);
    for (int ci = 0; ci < CG; ++ci) {
      float cav = s_ca[ci];
      #pragma unroll
      for (int k=0;k<2;++k) {
        int f = tid + NT*k;                    // 0..511
        int gi = ci*(HW/4) + hb*16 + f;
        float4 xv = gx4[gi];
        float4 wv = wv4[f];
        float4 ov;
        ov.x = xv.x * (cav * wv.x);
        ov.y = xv.y * (cav * wv.y);
        ov.z = xv.z * (cav * wv.z);
        ov.w = xv.w * (cav * wv.w);
        gout4[gi] = ov;
      }
    }
  }
}

extern "C" void kernel_launch(void* const* d_in, const int* in_sizes, int n_in,
                              void* d_out, int out_size) {
  (void)in_sizes; (void)n_in; (void)out_size;
  const int dyn2 = 2 * TILE2F * sizeof(float);   // 20736 B
  cudaFuncSetAttribute(ema_k2, cudaFuncAttributeMaxDynamicSharedMemorySize, dyn2);
  ema_k1<<<NGROUPS, NT>>>(
      (const float*)d_in[0],
      (const float*)d_in[1], (const float*)d_in[2],
      (const float*)d_in[3], (const float*)d_in[4],
      (const float*)d_in[5], (const float*)d_in[6],
      (const float*)d_in[7], (const float*)d_in[8],
      (const float*)d_in[9], (const float*)d_in[10]);
  ema_k2<<<2*NGROUPS, NT, dyn2>>>((const float*)d_in[0], (float*)d_out);
}